// round 16
// baseline (speedup 1.0000x reference)
#include <cuda_runtime.h>
#include <cuda_fp16.h>
#include <math.h>
#include <stdint.h>

#define NN 256
#define NC 3
#define NPLANES 384

// T stored pre-split as two fp16 planes; D stored as fp16 splits
__device__ __half g_T0[(size_t)NPLANES * NN * NN];
__device__ __half g_T1[(size_t)NPLANES * NN * NN];
__device__ __half g_Dh0[NN * NN];
__device__ __half g_Dh1[NN * NN];

// smem rows: 128B = 8 x 16B units, XOR-swizzled: unit_phys = unit_log ^ (row & 7)
#define ROWB 128
#define TILEA (128 * ROWB)   // 16384
#define TILEB_SZ (64 * ROWB) //  8192

// ---------------- helpers ----------------
__device__ __forceinline__ uint32_t smem_u32(const void* p) {
    uint32_t a;
    asm("{ .reg .u64 t; cvta.to.shared.u64 t, %1; cvt.u32.u64 %0, t; }" : "=r"(a) : "l"(p));
    return a;
}
__device__ __forceinline__ void ldsm_x4(uint32_t* r, uint32_t addr) {
    asm volatile("ldmatrix.sync.aligned.m8n8.x4.shared.b16 {%0,%1,%2,%3}, [%4];"
        : "=r"(r[0]), "=r"(r[1]), "=r"(r[2]), "=r"(r[3]) : "r"(addr));
}
__device__ __forceinline__ void mma_f16(float* d, const uint32_t* a, const uint32_t* b) {
    asm volatile("mma.sync.aligned.m16n8k16.row.col.f32.f16.f16.f32 "
        "{%0,%1,%2,%3}, {%4,%5,%6,%7}, {%8,%9}, {%0,%1,%2,%3};"
        : "+f"(d[0]), "+f"(d[1]), "+f"(d[2]), "+f"(d[3])
        : "r"(a[0]), "r"(a[1]), "r"(a[2]), "r"(a[3]), "r"(b[0]), "r"(b[1]));
}
__device__ __forceinline__ void mma_f16_z(float* d, const uint32_t* a, const uint32_t* b) {
    asm volatile("mma.sync.aligned.m16n8k16.row.col.f32.f16.f16.f32 "
        "{%0,%1,%2,%3}, {%4,%5,%6,%7}, {%8,%9}, {%10,%10,%10,%10};"
        : "=f"(d[0]), "=f"(d[1]), "=f"(d[2]), "=f"(d[3])
        : "r"(a[0]), "r"(a[1]), "r"(a[2]), "r"(a[3]), "r"(b[0]), "r"(b[1]), "f"(0.0f));
}
// packed master accumulate: m(f32x2) += {a1:a0}, rn per lane
__device__ __forceinline__ void madd2(unsigned long long& m, float a0, float a1) {
    asm("{\n\t.reg .b64 aa;\n\tmov.b64 aa, {%1, %2};\n\tadd.rn.f32x2 %0, %0, aa;\n\t}"
        : "+l"(m) : "f"(a0), "f"(a1));
}
__device__ __forceinline__ float2 unpk2(unsigned long long m) {
    float2 r;
    asm("mov.b64 {%0, %1}, %2;" : "=f"(r.x), "=f"(r.y) : "l"(m));
    return r;
}
__device__ __forceinline__ void split2(float v, uint16_t& s0, uint16_t& s1) {
    __half h0 = __float2half_rn(v);
    float r = v - __half2float(h0);
    __half h1 = __float2half_rn(r);
    s0 = __half_as_ushort(h0);
    s1 = __half_as_ushort(h1);
}
// packed pair split (bit-identical to scalar split2 per lane)
__device__ __forceinline__ void split2x2(float v0, float v1, uint32_t& h01, uint32_t& r01) {
    asm("cvt.rn.f16x2.f32 %0, %1, %2;" : "=r"(h01) : "f"(v1), "f"(v0));
    __half2 hh = *reinterpret_cast<__half2*>(&h01);
    float f0 = __half2float(__low2half(hh));
    float f1 = __half2float(__high2half(hh));
    asm("cvt.rn.f16x2.f32 %0, %1, %2;" : "=r"(r01) : "f"(v1 - f1), "f"(v0 - f0));
}

// ---- cp.async ----
__device__ __forceinline__ void cp16(uint32_t saddr, const void* gptr) {
    asm volatile("cp.async.cg.shared.global [%0], [%1], 16;" :: "r"(saddr), "l"(gptr));
}
// L1-cached variant for heavily reused tiles (D planes)
__device__ __forceinline__ void cp16ca(uint32_t saddr, const void* gptr) {
    asm volatile("cp.async.ca.shared.global [%0], [%1], 16;" :: "r"(saddr), "l"(gptr));
}
#define CP_COMMIT() asm volatile("cp.async.commit_group;" ::: "memory")
#define CP_WAIT0()  asm volatile("cp.async.wait_group 0;" ::: "memory")

__global__ void compute_D_kernel() {
    int k = blockIdx.x;
    int h = threadIdx.x;
    float a = 3.14159274101257324f * ((float)h + 0.5f);
    a = a * (float)k;
    a = a * 0.00390625f;
    float v = (float)cos((double)a);
    v = v * 0.088388347f;
    if (k == 0) v = v * 0.70710677f;
    uint16_t s0, s1;
    split2(v, s0, s1);
    int i = k * NN + h;
    g_Dh0[i] = __ushort_as_half(s0);
    g_Dh1[i] = __ushort_as_half(s1);
}

__device__ __forceinline__ float log_precise(float x) {
    unsigned ix = __float_as_uint(x);
    int e = (int)(ix >> 23) - 126;
    float m = __uint_as_float((ix & 0x007FFFFFu) | 0x3F000000u);
    if (m < 0.70710678f) { m = m + m; e -= 1; }
    float f = m - 1.0f;
    float z = f * f;
    float p =            7.0376836292e-2f;
    p = fmaf(p, f, -1.1514610310e-1f);
    p = fmaf(p, f,  1.1676998740e-1f);
    p = fmaf(p, f, -1.2420140846e-1f);
    p = fmaf(p, f,  1.4249322787e-1f);
    p = fmaf(p, f, -1.6668057665e-1f);
    p = fmaf(p, f,  2.0000714765e-1f);
    p = fmaf(p, f, -2.4999993993e-1f);
    p = fmaf(p, f,  3.3333331174e-1f);
    float y = f * z * p;
    float fe = (float)e;
    y = fmaf(fe, -2.12194440e-4f, y);
    y = fmaf(-0.5f, z, y);
    float r = f + y;
    r = fmaf(fe, 0.693359375f, r);
    return r;
}

// async copy of pre-split fp16 planes, full K=32 chunk, swizzled
template <bool CA>
__device__ __forceinline__ void async_fill_split(uint32_t smb, const __half* P0,
                                                 const __half* P1, int row0, int k0,
                                                 int tid, int nrows) {
    int row = tid >> 1, g = tid & 1;
    if (row < nrows) {
        uint32_t base = smb + row * ROWB;
        int x = row & 7;
        #pragma unroll
        for (int ph = 0; ph < 2; ph++) {
            size_t ga = (size_t)(row0 + row) * NN + k0 + ph * 16 + g * 8;
            if (CA) {
                cp16ca(base + (((ph * 2 + g)     ^ x) << 4), P0 + ga);
                cp16ca(base + (((4 + ph * 2 + g) ^ x) << 4), P1 + ga);
            } else {
                cp16(base + (((ph * 2 + g)     ^ x) << 4), P0 + ga);
                cp16(base + (((4 + ph * 2 + g) ^ x) << 4), P1 + ga);
            }
        }
    }
}

// ---- GEMM1 B tile: gather fp32 x (stride-3), packed split-store, per 16-col phase ----
struct B1Half { float v[4]; };
__device__ __forceinline__ void gather_B1h(B1Half& br, const float* xb, int h0k,
                                           int tw, int tid) {
    int n = tid & 63, ks = tid >> 6;
    const float* px = xb + (size_t)(h0k + ks * 4) * (NN * NC) + (size_t)(tw + n) * NC;
    #pragma unroll
    for (int i = 0; i < 4; i++) br.v[i] = px[(size_t)i * (NN * NC)];
}
__device__ __forceinline__ void store_B1h(uint8_t* sB, const B1Half& br, int ph, int tid) {
    int n = tid & 63, ks = tid >> 6;
    uint32_t h01, r01, h23, r23;
    split2x2(br.v[0], br.v[1], h01, r01);
    split2x2(br.v[2], br.v[3], h23, r23);
    int x = n & 7;
    int ul0 = ph * 2 + (ks >> 1);
    int ul1 = 4 + ph * 2 + (ks >> 1);
    int sub = (ks & 1) * 8;
    uint8_t* base = sB + n * ROWB;
    *(uint2*)(base + ((ul0 ^ x) << 4) + sub) = make_uint2(h01, h23);
    *(uint2*)(base + ((ul1 ^ x) << 4) + sub) = make_uint2(r01, r23);
}

// one (A,B) product block: 2x4 mmas (width-8 independent — R11 form)
template <bool Z>
__device__ __forceinline__ void mma_blk(float acc[2][4][4], const uint32_t af[2][4],
                                        const uint32_t bf[2][4]) {
    #pragma unroll
    for (int mt = 0; mt < 2; mt++)
        #pragma unroll
        for (int nt = 0; nt < 4; nt++) {
            if (Z) mma_f16_z(acc[mt][nt], af[mt], &bf[nt >> 1][(nt & 1) * 2]);
            else   mma_f16  (acc[mt][nt], af[mt], &bf[nt >> 1][(nt & 1) * 2]);
        }
}

// one 16-k sub-chunk: 8 ldsm, 24 mmas (smalls fresh-first, big last),
// master += acc (packed rn). Arithmetic identical to R10/R11.
__device__ __forceinline__ void mma_sub(uint32_t aRow, uint32_t bRow,
                                        unsigned long long master[2][4][2],
                                        int khA, int xA, int khB, int xB, int kc) {
    uint32_t a0f[2][4], a1f[2][4], b0f[2][4], b1f[2][4];
    #pragma unroll
    for (int mt = 0; mt < 2; mt++) {
        uint32_t rowOff = aRow + mt * 16 * ROWB;
        ldsm_x4(a0f[mt], rowOff + ((((kc * 2 + khA)    ) ^ xA) << 4));
        ldsm_x4(a1f[mt], rowOff + ((((kc * 2 + khA) + 4) ^ xA) << 4));
    }
    #pragma unroll
    for (int h2 = 0; h2 < 2; h2++) {
        uint32_t rowOff = bRow + h2 * 16 * ROWB;
        ldsm_x4(b0f[h2], rowOff + ((((kc * 2 + khB)    ) ^ xB) << 4));
        ldsm_x4(b1f[h2], rowOff + ((((kc * 2 + khB) + 4) ^ xB) << 4));
    }

    float acc[2][4][4];
    mma_blk<true >(acc, a0f, b1f);   // big x small (fresh)
    mma_blk<false>(acc, a1f, b0f);   // small x big
    mma_blk<false>(acc, a0f, b0f);   // big x big (last: one big rounding)

    #pragma unroll
    for (int mt = 0; mt < 2; mt++)
        #pragma unroll
        for (int nt = 0; nt < 4; nt++) {
            madd2(master[mt][nt][0], acc[mt][nt][0], acc[mt][nt][1]);
            madd2(master[mt][nt][1], acc[mt][nt][2], acc[mt][nt][3]);
        }
}

#define ZERO_ACC(A)                                        \
    _Pragma("unroll") for (int i = 0; i < 2; i++)          \
    _Pragma("unroll") for (int j = 0; j < 4; j++)          \
    _Pragma("unroll") for (int e = 0; e < 2; e++) A[i][j][e] = 0ull;

// ---------------------------------------------------------------------------
// GEMM1: T[k,w] = sum_h D[k,h] * x[b,h,w,c];  CTA tile 128(k) x 64(w), K-chunk 32
// (exact R11 form; A fill .ca since D is reused by all CTAs)
// ---------------------------------------------------------------------------
__global__ void __launch_bounds__(256, 2) dct_gemm1(const float* __restrict__ x) {
    __shared__ __align__(16) uint8_t sA[2][TILEA];
    __shared__ __align__(16) uint8_t sB[2][TILEB_SZ];
    int tid = threadIdx.x, wid = tid >> 5, lane = tid & 31;
    int warp_m = wid & 3, warp_n = wid >> 2;
    int p = blockIdx.y, b = p / 3, c = p - 3 * b;
    int tk = (blockIdx.x >> 2) * 128, tw = (blockIdx.x & 3) * 64;
    const float* xb = x + (size_t)b * NN * NN * NC + c;

    uint32_t sAb[2] = { smem_u32(sA[0]), smem_u32(sA[1]) };

    int rA = lane & 15, khA = lane >> 4, xA = rA & 7;
    int rB = ((lane >> 4) & 1) * 8 + (lane & 7), khB = (lane >> 3) & 1, xB = lane & 7;
    uint32_t aRowB[2] = { sAb[0] + (warp_m * 32 + rA) * ROWB, sAb[1] + (warp_m * 32 + rA) * ROWB };
    uint32_t bRowB[2] = { smem_u32(sB[0]) + (warp_n * 32 + rB) * ROWB,
                          smem_u32(sB[1]) + (warp_n * 32 + rB) * ROWB };

    unsigned long long master[2][4][2];
    ZERO_ACC(master);

    {   // prologue: fill buf 0
        async_fill_split<true>(sAb[0], g_Dh0, g_Dh1, tk, 0, tid, 128);
        CP_COMMIT();
        B1Half hb;
        gather_B1h(hb, xb, 0, tw, tid);
        store_B1h(sB[0], hb, 0, tid);
        gather_B1h(hb, xb, 16, tw, tid);
        store_B1h(sB[0], hb, 1, tid);
        CP_WAIT0();
    }
    __syncthreads();

    #pragma unroll 1
    for (int t = 0; t < 8; t++) {
        int buf = t & 1;
        int h0n = (t + 1) * 32;
        B1Half hb;
        if (t < 7) {
            async_fill_split<true>(sAb[buf ^ 1], g_Dh0, g_Dh1, tk, h0n, tid, 128);
            CP_COMMIT();
            gather_B1h(hb, xb, h0n, tw, tid);
        }
        mma_sub(aRowB[buf], bRowB[buf], master, khA, xA, khB, xB, 0);
        if (t < 7) {
            store_B1h(sB[buf ^ 1], hb, 0, tid);
            gather_B1h(hb, xb, h0n + 16, tw, tid);
        }
        mma_sub(aRowB[buf], bRowB[buf], master, khA, xA, khB, xB, 1);
        if (t < 7) {
            store_B1h(sB[buf ^ 1], hb, 1, tid);
            CP_WAIT0();
        }
        __syncthreads();
    }

    // epilogue: split T to fp16 planes (packed cvts, bit-identical)
    __half* T0 = g_T0 + (size_t)p * NN * NN;
    __half* T1 = g_T1 + (size_t)p * NN * NN;
    int r = lane >> 2, q = (lane & 3) * 2;
    #pragma unroll
    for (int mt = 0; mt < 2; mt++) {
        int m0 = tk + warp_m * 32 + mt * 16 + r;
        #pragma unroll
        for (int nt = 0; nt < 4; nt++) {
            int ncol = tw + warp_n * 32 + nt * 8 + q;
            #pragma unroll
            for (int hh = 0; hh < 2; hh++) {
                int row = m0 + hh * 8;
                float2 v = unpk2(master[mt][nt][hh]);
                uint32_t t0p, t1p;
                split2x2(v.x, v.y, t0p, t1p);
                *(uint32_t*)(T0 + (size_t)row * NN + ncol) = t0p;
                *(uint32_t*)(T1 + (size_t)row * NN + ncol) = t1p;
            }
        }
    }
}

// ---------------------------------------------------------------------------
// GEMM2: U[k,j] = sum_w T[k,w] * D[j,w]; 2-stage static-smem pipeline (exact
// R11 form; B fill .ca since D is reused, A (T) stays .cg streaming)
// ---------------------------------------------------------------------------
__global__ void __launch_bounds__(256, 2) dct_gemm2(const float* __restrict__ mean,
                                                    const float* __restrict__ stdv,
                                                    float* __restrict__ out) {
    __shared__ __align__(16) uint8_t sA[2][TILEA];
    __shared__ __align__(16) uint8_t sB[2][TILEB_SZ];
    int tid = threadIdx.x, wid = tid >> 5, lane = tid & 31;
    int warp_m = wid & 3, warp_n = wid >> 2;
    int p = blockIdx.y, b = p / 3, c = p - 3 * b;
    int tk = (blockIdx.x >> 2) * 128, tj = (blockIdx.x & 3) * 64;
    const __half* T0 = g_T0 + (size_t)p * NN * NN;
    const __half* T1 = g_T1 + (size_t)p * NN * NN;

    uint32_t sAb[2] = { smem_u32(sA[0]), smem_u32(sA[1]) };
    uint32_t sBb[2] = { smem_u32(sB[0]), smem_u32(sB[1]) };

    int rA = lane & 15, khA = lane >> 4, xA = rA & 7;
    int rB = ((lane >> 4) & 1) * 8 + (lane & 7), khB = (lane >> 3) & 1, xB = lane & 7;
    uint32_t aRowB[2] = { sAb[0] + (warp_m * 32 + rA) * ROWB, sAb[1] + (warp_m * 32 + rA) * ROWB };
    uint32_t bRowB[2] = { sBb[0] + (warp_n * 32 + rB) * ROWB, sBb[1] + (warp_n * 32 + rB) * ROWB };

    unsigned long long master[2][4][2];
    ZERO_ACC(master);

    async_fill_split<false>(sAb[0], T0, T1, tk, 0, tid, 128);
    async_fill_split<true >(sBb[0], g_Dh0, g_Dh1, tj, 0, tid, 64);
    CP_COMMIT();
    CP_WAIT0();
    __syncthreads();

    #pragma unroll 1
    for (int t = 0; t < 8; t++) {
        int buf = t & 1;
        int w0n = (t + 1) * 32;
        if (t < 7) {
            async_fill_split<false>(sAb[buf ^ 1], T0, T1, tk, w0n, tid, 128);
            async_fill_split<true >(sBb[buf ^ 1], g_Dh0, g_Dh1, tj, w0n, tid, 64);
            CP_COMMIT();
        }
        mma_sub(aRowB[buf], bRowB[buf], master, khA, xA, khB, xB, 0);
        mma_sub(aRowB[buf], bRowB[buf], master, khA, xA, khB, xB, 1);
        if (t < 7) CP_WAIT0();
        __syncthreads();
    }

    int r = lane >> 2, q = (lane & 3) * 2;
    #pragma unroll
    for (int mt = 0; mt < 2; mt++) {
        #pragma unroll
        for (int nt = 0; nt < 4; nt++) {
            #pragma unroll
            for (int hh = 0; hh < 2; hh++) {
                float2 v = unpk2(master[mt][nt][hh]);
                int krow = tk + warp_m * 32 + mt * 16 + r + hh * 8;
                int j0 = tj + warp_n * 32 + nt * 8 + q;
                float z0 = log_precise(fabsf(v.x) + 1e-13f);
                float z1 = log_precise(fabsf(v.y) + 1e-13f);
                int mi0 = (krow * NN + j0) * NC + c;
                int mi1 = mi0 + NC;
                size_t ob = ((size_t)(b * NN + krow) * NN + j0) * NC + c;
                out[ob]      = (z0 - mean[mi0]) / stdv[mi0];
                out[ob + NC] = (z1 - mean[mi1]) / stdv[mi1];
            }
        }
    }
}

// ---------------------------------------------------------------------------
extern "C" void kernel_launch(void* const* d_in, const int* in_sizes, int n_in,
                              void* d_out, int out_size) {
    const float* x    = (const float*)d_in[0];
    const float* mean = (const float*)d_in[1];
    const float* stdv = (const float*)d_in[2];
    float* out = (float*)d_out;

    compute_D_kernel<<<256, 256>>>();
    dct_gemm1<<<dim3(8, NPLANES), 256>>>(x);
    dct_gemm2<<<dim3(8, NPLANES), 256>>>(mean, stdv, out);
}

// round 17
// speedup vs baseline: 1.2525x; 1.2525x over previous
#include <cuda_runtime.h>
#include <cuda_fp16.h>
#include <math.h>
#include <stdint.h>

#define NN 256
#define NC 3
#define NPLANES 384

// T stored pre-split as two fp16 planes; D stored as fp16 splits
__device__ __half g_T0[(size_t)NPLANES * NN * NN];
__device__ __half g_T1[(size_t)NPLANES * NN * NN];
__device__ __half g_Dh0[NN * NN];
__device__ __half g_Dh1[NN * NN];
// packed per-channel (mean, 1/std): g_MS[c][row][j]
__device__ float2 g_MS[(size_t)NC * NN * NN];

// smem rows: 128B = 8 x 16B units, XOR-swizzled: unit_phys = unit_log ^ (row & 7)
#define ROWB 128
#define TILEA (128 * ROWB)   // 16384
#define TILEB_SZ (64 * ROWB) //  8192

// ---------------- helpers ----------------
__device__ __forceinline__ uint32_t smem_u32(const void* p) {
    uint32_t a;
    asm("{ .reg .u64 t; cvta.to.shared.u64 t, %1; cvt.u32.u64 %0, t; }" : "=r"(a) : "l"(p));
    return a;
}
__device__ __forceinline__ void ldsm_x4(uint32_t* r, uint32_t addr) {
    asm volatile("ldmatrix.sync.aligned.m8n8.x4.shared.b16 {%0,%1,%2,%3}, [%4];"
        : "=r"(r[0]), "=r"(r[1]), "=r"(r[2]), "=r"(r[3]) : "r"(addr));
}
__device__ __forceinline__ void mma_f16(float* d, const uint32_t* a, const uint32_t* b) {
    asm volatile("mma.sync.aligned.m16n8k16.row.col.f32.f16.f16.f32 "
        "{%0,%1,%2,%3}, {%4,%5,%6,%7}, {%8,%9}, {%0,%1,%2,%3};"
        : "+f"(d[0]), "+f"(d[1]), "+f"(d[2]), "+f"(d[3])
        : "r"(a[0]), "r"(a[1]), "r"(a[2]), "r"(a[3]), "r"(b[0]), "r"(b[1]));
}
__device__ __forceinline__ void mma_f16_z(float* d, const uint32_t* a, const uint32_t* b) {
    asm volatile("mma.sync.aligned.m16n8k16.row.col.f32.f16.f16.f32 "
        "{%0,%1,%2,%3}, {%4,%5,%6,%7}, {%8,%9}, {%10,%10,%10,%10};"
        : "=f"(d[0]), "=f"(d[1]), "=f"(d[2]), "=f"(d[3])
        : "r"(a[0]), "r"(a[1]), "r"(a[2]), "r"(a[3]), "r"(b[0]), "r"(b[1]), "f"(0.0f));
}
// packed master accumulate: m(f32x2) += {a1:a0}, rn per lane
__device__ __forceinline__ void madd2(unsigned long long& m, float a0, float a1) {
    asm("{\n\t.reg .b64 aa;\n\tmov.b64 aa, {%1, %2};\n\tadd.rn.f32x2 %0, %0, aa;\n\t}"
        : "+l"(m) : "f"(a0), "f"(a1));
}
__device__ __forceinline__ float2 unpk2(unsigned long long m) {
    float2 r;
    asm("mov.b64 {%0, %1}, %2;" : "=f"(r.x), "=f"(r.y) : "l"(m));
    return r;
}
__device__ __forceinline__ void split2(float v, uint16_t& s0, uint16_t& s1) {
    __half h0 = __float2half_rn(v);
    float r = v - __half2float(h0);
    __half h1 = __float2half_rn(r);
    s0 = __half_as_ushort(h0);
    s1 = __half_as_ushort(h1);
}
// packed pair split (bit-identical to scalar split2 per lane)
__device__ __forceinline__ void split2x2(float v0, float v1, uint32_t& h01, uint32_t& r01) {
    asm("cvt.rn.f16x2.f32 %0, %1, %2;" : "=r"(h01) : "f"(v1), "f"(v0));
    __half2 hh = *reinterpret_cast<__half2*>(&h01);
    float f0 = __half2float(__low2half(hh));
    float f1 = __half2float(__high2half(hh));
    asm("cvt.rn.f16x2.f32 %0, %1, %2;" : "=r"(r01) : "f"(v1 - f1), "f"(v0 - f0));
}

// ---- cp.async ----
__device__ __forceinline__ void cp16(uint32_t saddr, const void* gptr) {
    asm volatile("cp.async.cg.shared.global [%0], [%1], 16;" :: "r"(saddr), "l"(gptr));
}
#define CP_COMMIT() asm volatile("cp.async.commit_group;" ::: "memory")
#define CP_WAIT0()  asm volatile("cp.async.wait_group 0;" ::: "memory")

__global__ void compute_D_kernel() {
    int k = blockIdx.x;
    int h = threadIdx.x;
    float a = 3.14159274101257324f * ((float)h + 0.5f);
    a = a * (float)k;
    a = a * 0.00390625f;
    float v = (float)cos((double)a);
    v = v * 0.088388347f;
    if (k == 0) v = v * 0.70710677f;
    uint16_t s0, s1;
    split2(v, s0, s1);
    int i = k * NN + h;
    g_Dh0[i] = __ushort_as_half(s0);
    g_Dh1[i] = __ushort_as_half(s1);
}

// repack (mean, 1/std) into channel-planar float2
__global__ void prepack_ms(const float* __restrict__ mean,
                           const float* __restrict__ stdv) {
    int row = blockIdx.x, c = blockIdx.y, j = threadIdx.x;
    int src = (row * NN + j) * NC + c;
    g_MS[((size_t)c * NN + row) * NN + j] =
        make_float2(mean[src], __frcp_rn(stdv[src]));
}

__device__ __forceinline__ float log_precise(float x) {
    unsigned ix = __float_as_uint(x);
    int e = (int)(ix >> 23) - 126;
    float m = __uint_as_float((ix & 0x007FFFFFu) | 0x3F000000u);
    if (m < 0.70710678f) { m = m + m; e -= 1; }
    float f = m - 1.0f;
    float z = f * f;
    float p =            7.0376836292e-2f;
    p = fmaf(p, f, -1.1514610310e-1f);
    p = fmaf(p, f,  1.1676998740e-1f);
    p = fmaf(p, f, -1.2420140846e-1f);
    p = fmaf(p, f,  1.4249322787e-1f);
    p = fmaf(p, f, -1.6668057665e-1f);
    p = fmaf(p, f,  2.0000714765e-1f);
    p = fmaf(p, f, -2.4999993993e-1f);
    p = fmaf(p, f,  3.3333331174e-1f);
    float y = f * z * p;
    float fe = (float)e;
    y = fmaf(fe, -2.12194440e-4f, y);
    y = fmaf(-0.5f, z, y);
    float r = f + y;
    r = fmaf(fe, 0.693359375f, r);
    return r;
}

// async copy of pre-split fp16 planes, full K=32 chunk, swizzled (.cg only)
__device__ __forceinline__ void async_fill_split(uint32_t smb, const __half* P0,
                                                 const __half* P1, int row0, int k0,
                                                 int tid, int nrows) {
    int row = tid >> 1, g = tid & 1;
    if (row < nrows) {
        uint32_t base = smb + row * ROWB;
        int x = row & 7;
        #pragma unroll
        for (int ph = 0; ph < 2; ph++) {
            size_t ga = (size_t)(row0 + row) * NN + k0 + ph * 16 + g * 8;
            cp16(base + (((ph * 2 + g)     ^ x) << 4), P0 + ga);
            cp16(base + (((4 + ph * 2 + g) ^ x) << 4), P1 + ga);
        }
    }
}

// ---- GEMM1 B tile: gather fp32 x (stride-3), packed split-store, per 16-col phase ----
struct B1Half { float v[4]; };
__device__ __forceinline__ void gather_B1h(B1Half& br, const float* xb, int h0k,
                                           int tw, int tid) {
    int n = tid & 63, ks = tid >> 6;
    const float* px = xb + (size_t)(h0k + ks * 4) * (NN * NC) + (size_t)(tw + n) * NC;
    #pragma unroll
    for (int i = 0; i < 4; i++) br.v[i] = px[(size_t)i * (NN * NC)];
}
__device__ __forceinline__ void store_B1h(uint8_t* sB, const B1Half& br, int ph, int tid) {
    int n = tid & 63, ks = tid >> 6;
    uint32_t h01, r01, h23, r23;
    split2x2(br.v[0], br.v[1], h01, r01);
    split2x2(br.v[2], br.v[3], h23, r23);
    int x = n & 7;
    int ul0 = ph * 2 + (ks >> 1);
    int ul1 = 4 + ph * 2 + (ks >> 1);
    int sub = (ks & 1) * 8;
    uint8_t* base = sB + n * ROWB;
    *(uint2*)(base + ((ul0 ^ x) << 4) + sub) = make_uint2(h01, h23);
    *(uint2*)(base + ((ul1 ^ x) << 4) + sub) = make_uint2(r01, r23);
}

// one (A,B) product block: 2x4 mmas (width-8 independent — R11 form)
template <bool Z>
__device__ __forceinline__ void mma_blk(float acc[2][4][4], const uint32_t af[2][4],
                                        const uint32_t bf[2][4]) {
    #pragma unroll
    for (int mt = 0; mt < 2; mt++)
        #pragma unroll
        for (int nt = 0; nt < 4; nt++) {
            if (Z) mma_f16_z(acc[mt][nt], af[mt], &bf[nt >> 1][(nt & 1) * 2]);
            else   mma_f16  (acc[mt][nt], af[mt], &bf[nt >> 1][(nt & 1) * 2]);
        }
}

// one 16-k sub-chunk: 8 ldsm, 24 mmas (smalls fresh-first, big last),
// master += acc (packed rn). Arithmetic identical to R10/R11.
__device__ __forceinline__ void mma_sub(uint32_t aRow, uint32_t bRow,
                                        unsigned long long master[2][4][2],
                                        int khA, int xA, int khB, int xB, int kc) {
    uint32_t a0f[2][4], a1f[2][4], b0f[2][4], b1f[2][4];
    #pragma unroll
    for (int mt = 0; mt < 2; mt++) {
        uint32_t rowOff = aRow + mt * 16 * ROWB;
        ldsm_x4(a0f[mt], rowOff + ((((kc * 2 + khA)    ) ^ xA) << 4));
        ldsm_x4(a1f[mt], rowOff + ((((kc * 2 + khA) + 4) ^ xA) << 4));
    }
    #pragma unroll
    for (int h2 = 0; h2 < 2; h2++) {
        uint32_t rowOff = bRow + h2 * 16 * ROWB;
        ldsm_x4(b0f[h2], rowOff + ((((kc * 2 + khB)    ) ^ xB) << 4));
        ldsm_x4(b1f[h2], rowOff + ((((kc * 2 + khB) + 4) ^ xB) << 4));
    }

    float acc[2][4][4];
    mma_blk<true >(acc, a0f, b1f);   // big x small (fresh)
    mma_blk<false>(acc, a1f, b0f);   // small x big
    mma_blk<false>(acc, a0f, b0f);   // big x big (last: one big rounding)

    #pragma unroll
    for (int mt = 0; mt < 2; mt++)
        #pragma unroll
        for (int nt = 0; nt < 4; nt++) {
            madd2(master[mt][nt][0], acc[mt][nt][0], acc[mt][nt][1]);
            madd2(master[mt][nt][1], acc[mt][nt][2], acc[mt][nt][3]);
        }
}

#define ZERO_ACC(A)                                        \
    _Pragma("unroll") for (int i = 0; i < 2; i++)          \
    _Pragma("unroll") for (int j = 0; j < 4; j++)          \
    _Pragma("unroll") for (int e = 0; e < 2; e++) A[i][j][e] = 0ull;

// ---------------------------------------------------------------------------
// GEMM1: T[k,w] = sum_h D[k,h] * x[b,h,w,c];  CTA tile 128(k) x 64(w), K-chunk 32
// (exact R11 form)
// ---------------------------------------------------------------------------
__global__ void __launch_bounds__(256, 2) dct_gemm1(const float* __restrict__ x) {
    __shared__ __align__(16) uint8_t sA[2][TILEA];
    __shared__ __align__(16) uint8_t sB[2][TILEB_SZ];
    int tid = threadIdx.x, wid = tid >> 5, lane = tid & 31;
    int warp_m = wid & 3, warp_n = wid >> 2;
    int p = blockIdx.y, b = p / 3, c = p - 3 * b;
    int tk = (blockIdx.x >> 2) * 128, tw = (blockIdx.x & 3) * 64;
    const float* xb = x + (size_t)b * NN * NN * NC + c;

    uint32_t sAb[2] = { smem_u32(sA[0]), smem_u32(sA[1]) };

    int rA = lane & 15, khA = lane >> 4, xA = rA & 7;
    int rB = ((lane >> 4) & 1) * 8 + (lane & 7), khB = (lane >> 3) & 1, xB = lane & 7;
    uint32_t aRowB[2] = { sAb[0] + (warp_m * 32 + rA) * ROWB, sAb[1] + (warp_m * 32 + rA) * ROWB };
    uint32_t bRowB[2] = { smem_u32(sB[0]) + (warp_n * 32 + rB) * ROWB,
                          smem_u32(sB[1]) + (warp_n * 32 + rB) * ROWB };

    unsigned long long master[2][4][2];
    ZERO_ACC(master);

    {   // prologue: fill buf 0
        async_fill_split(sAb[0], g_Dh0, g_Dh1, tk, 0, tid, 128);
        CP_COMMIT();
        B1Half hb;
        gather_B1h(hb, xb, 0, tw, tid);
        store_B1h(sB[0], hb, 0, tid);
        gather_B1h(hb, xb, 16, tw, tid);
        store_B1h(sB[0], hb, 1, tid);
        CP_WAIT0();
    }
    __syncthreads();

    #pragma unroll 1
    for (int t = 0; t < 8; t++) {
        int buf = t & 1;
        int h0n = (t + 1) * 32;
        B1Half hb;
        if (t < 7) {
            async_fill_split(sAb[buf ^ 1], g_Dh0, g_Dh1, tk, h0n, tid, 128);
            CP_COMMIT();
            gather_B1h(hb, xb, h0n, tw, tid);
        }
        mma_sub(aRowB[buf], bRowB[buf], master, khA, xA, khB, xB, 0);
        if (t < 7) {
            store_B1h(sB[buf ^ 1], hb, 0, tid);
            gather_B1h(hb, xb, h0n + 16, tw, tid);
        }
        mma_sub(aRowB[buf], bRowB[buf], master, khA, xA, khB, xB, 1);
        if (t < 7) {
            store_B1h(sB[buf ^ 1], hb, 1, tid);
            CP_WAIT0();
        }
        __syncthreads();
    }

    // epilogue: split T to fp16 planes (packed cvts, bit-identical)
    __half* T0 = g_T0 + (size_t)p * NN * NN;
    __half* T1 = g_T1 + (size_t)p * NN * NN;
    int r = lane >> 2, q = (lane & 3) * 2;
    #pragma unroll
    for (int mt = 0; mt < 2; mt++) {
        int m0 = tk + warp_m * 32 + mt * 16 + r;
        #pragma unroll
        for (int nt = 0; nt < 4; nt++) {
            int ncol = tw + warp_n * 32 + nt * 8 + q;
            #pragma unroll
            for (int hh = 0; hh < 2; hh++) {
                int row = m0 + hh * 8;
                float2 v = unpk2(master[mt][nt][hh]);
                uint32_t t0p, t1p;
                split2x2(v.x, v.y, t0p, t1p);
                *(uint32_t*)(T0 + (size_t)row * NN + ncol) = t0p;
                *(uint32_t*)(T1 + (size_t)row * NN + ncol) = t1p;
            }
        }
    }
}

// ---------------------------------------------------------------------------
// GEMM2: U[k,j] = sum_w T[k,w] * D[j,w]; 2-stage static-smem pipeline (exact
// R11 mainloop); epilogue uses packed (mean, 1/std) float4 loads + FMUL.
// ---------------------------------------------------------------------------
__global__ void __launch_bounds__(256, 2) dct_gemm2(float* __restrict__ out) {
    __shared__ __align__(16) uint8_t sA[2][TILEA];
    __shared__ __align__(16) uint8_t sB[2][TILEB_SZ];
    int tid = threadIdx.x, wid = tid >> 5, lane = tid & 31;
    int warp_m = wid & 3, warp_n = wid >> 2;
    int p = blockIdx.y, b = p / 3, c = p - 3 * b;
    int tk = (blockIdx.x >> 2) * 128, tj = (blockIdx.x & 3) * 64;
    const __half* T0 = g_T0 + (size_t)p * NN * NN;
    const __half* T1 = g_T1 + (size_t)p * NN * NN;

    uint32_t sAb[2] = { smem_u32(sA[0]), smem_u32(sA[1]) };
    uint32_t sBb[2] = { smem_u32(sB[0]), smem_u32(sB[1]) };

    int rA = lane & 15, khA = lane >> 4, xA = rA & 7;
    int rB = ((lane >> 4) & 1) * 8 + (lane & 7), khB = (lane >> 3) & 1, xB = lane & 7;
    uint32_t aRowB[2] = { sAb[0] + (warp_m * 32 + rA) * ROWB, sAb[1] + (warp_m * 32 + rA) * ROWB };
    uint32_t bRowB[2] = { sBb[0] + (warp_n * 32 + rB) * ROWB, sBb[1] + (warp_n * 32 + rB) * ROWB };

    unsigned long long master[2][4][2];
    ZERO_ACC(master);

    async_fill_split(sAb[0], T0, T1, tk, 0, tid, 128);
    async_fill_split(sBb[0], g_Dh0, g_Dh1, tj, 0, tid, 64);
    CP_COMMIT();
    CP_WAIT0();
    __syncthreads();

    #pragma unroll 1
    for (int t = 0; t < 8; t++) {
        int buf = t & 1;
        int w0n = (t + 1) * 32;
        if (t < 7) {
            async_fill_split(sAb[buf ^ 1], T0, T1, tk, w0n, tid, 128);
            async_fill_split(sBb[buf ^ 1], g_Dh0, g_Dh1, tj, w0n, tid, 64);
            CP_COMMIT();
        }
        mma_sub(aRowB[buf], bRowB[buf], master, khA, xA, khB, xB, 0);
        mma_sub(aRowB[buf], bRowB[buf], master, khA, xA, khB, xB, 1);
        if (t < 7) CP_WAIT0();
        __syncthreads();
    }

    const float2* MS = g_MS + (size_t)c * NN * NN;
    int r = lane >> 2, q = (lane & 3) * 2;
    #pragma unroll
    for (int mt = 0; mt < 2; mt++) {
        #pragma unroll
        for (int nt = 0; nt < 4; nt++) {
            #pragma unroll
            for (int hh = 0; hh < 2; hh++) {
                float2 v = unpk2(master[mt][nt][hh]);
                int krow = tk + warp_m * 32 + mt * 16 + r + hh * 8;
                int j0 = tj + warp_n * 32 + nt * 8 + q;
                float z0 = log_precise(fabsf(v.x) + 1e-13f);
                float z1 = log_precise(fabsf(v.y) + 1e-13f);
                float4 ms = *(const float4*)(MS + (size_t)krow * NN + j0);
                size_t ob = ((size_t)(b * NN + krow) * NN + j0) * NC + c;
                out[ob]      = (z0 - ms.x) * ms.y;
                out[ob + NC] = (z1 - ms.z) * ms.w;
            }
        }
    }
}

// ---------------------------------------------------------------------------
extern "C" void kernel_launch(void* const* d_in, const int* in_sizes, int n_in,
                              void* d_out, int out_size) {
    const float* x    = (const float*)d_in[0];
    const float* mean = (const float*)d_in[1];
    const float* stdv = (const float*)d_in[2];
    float* out = (float*)d_out;

    compute_D_kernel<<<256, 256>>>();
    prepack_ms<<<dim3(NN, NC), NN>>>(mean, stdv);
    dct_gemm1<<<dim3(8, NPLANES), 256>>>(x);
    dct_gemm2<<<dim3(8, NPLANES), 256>>>(out);
}